// round 10
// baseline (speedup 1.0000x reference)
#include <cuda_runtime.h>
#include <cstdint>

// LTC scan, round 10.
// R9 post-mortem: 1515us plateau across 3 tail structures => near a real floor;
// FFMA2 reads 3 reg-pairs -> RF-bank rt=3 (not 2); tails + SEL/IMAD fma-pipe
// pollution account for the rest.
// R10: (a) tanh.approx.f32 (MUFU.TANH) replaces the EX2/RCP chain (~48cyc serial
// + 4 fma-pipe ops saved per state); (b) mine/other row POINTERS precomputed ->
// zero SELs, zero per-unfold address IMADs; (c) FFMA2s ordered so the h operand
// is consecutively reused (.reuse lowers effective bank-conflict rt).

#define Bsz 512
#define Ssz 512
#define Dsz 128
#define Hsz 128
#define UNFOLDS 6
#define HSTRIDE 136   // 128 + 4 (pad at k=64) + 4 (row-stride bank shift)

typedef unsigned long long ull;

__device__ float g_xin[(size_t)Bsz * Ssz * Hsz];   // [b][s][h] scratch

__device__ __forceinline__ ull ffma2(ull a, ull b, ull c) {
    ull d;
    asm("fma.rn.f32x2 %0, %1, %2, %3;" : "=l"(d) : "l"(a), "l"(b), "l"(c));
    return d;
}

__device__ __forceinline__ float f2sum(ull v) {
    float lo, hi;
    asm("mov.b64 {%0, %1}, %2;" : "=f"(lo), "=f"(hi) : "l"(v));
    return lo + hi;
}

__device__ __forceinline__ float ftanh(float s) {
    float y;
    asm("tanh.approx.f32 %0, %1;" : "=f"(y) : "f"(s));   // MUFU.TANH
    return y;
}

// ---------------------------------------------------------------------------
// Kernel 1: xin[b,s,j] = sum_d x[b,s,d] * W_in[j,d] + b_in[j]
// ---------------------------------------------------------------------------
__global__ void __launch_bounds__(128, 2)
xin_kernel(const float* __restrict__ x,
           const float* __restrict__ W_in,
           const float* __restrict__ b_in)
{
    __shared__ float xs[2][4 * Dsz];

    const int j = threadIdx.x;

    ull wi[64];
    {
        const ulonglong2* wp = (const ulonglong2*)(W_in + j * Dsz);
        #pragma unroll
        for (int c = 0; c < 32; ++c) {
            ulonglong2 v = wp[c];
            wi[2 * c]     = v.x;
            wi[2 * c + 1] = v.y;
        }
    }
    const float bi = b_in[j];

    const int m0 = blockIdx.x * 128;

    float xf[4];
    #pragma unroll
    for (int r = 0; r < 4; ++r)
        xf[r] = x[(size_t)(m0 + r) * Dsz + j];

    #pragma unroll 1
    for (int ch = 0; ch < 32; ++ch) {
        float* xb = xs[ch & 1];
        #pragma unroll
        for (int r = 0; r < 4; ++r)
            xb[r * Dsz + j] = xf[r];
        __syncthreads();

        if (ch < 31) {
            #pragma unroll
            for (int r = 0; r < 4; ++r)
                xf[r] = x[(size_t)(m0 + (ch + 1) * 4 + r) * Dsz + j];
        }

        ull a0 = 0ull, a1 = 0ull, a2 = 0ull, a3 = 0ull;
        ull a4 = 0ull, a5 = 0ull, a6 = 0ull, a7 = 0ull;
        #pragma unroll
        for (int c = 0; c < 32; ++c) {
            ulonglong2 v0 = *(const ulonglong2*)(xb + 0 * Dsz + 4 * c);
            ulonglong2 v1 = *(const ulonglong2*)(xb + 1 * Dsz + 4 * c);
            ulonglong2 v2 = *(const ulonglong2*)(xb + 2 * Dsz + 4 * c);
            ulonglong2 v3 = *(const ulonglong2*)(xb + 3 * Dsz + 4 * c);
            a0 = ffma2(wi[2 * c], v0.x, a0);  a1 = ffma2(wi[2 * c + 1], v0.y, a1);
            a2 = ffma2(wi[2 * c], v1.x, a2);  a3 = ffma2(wi[2 * c + 1], v1.y, a3);
            a4 = ffma2(wi[2 * c], v2.x, a4);  a5 = ffma2(wi[2 * c + 1], v2.y, a5);
            a6 = ffma2(wi[2 * c], v3.x, a6);  a7 = ffma2(wi[2 * c + 1], v3.y, a7);
        }
        const int m = m0 + ch * 4;
        g_xin[(size_t)(m + 0) * Hsz + j] = f2sum(a0) + f2sum(a1) + bi;
        g_xin[(size_t)(m + 1) * Hsz + j] = f2sum(a2) + f2sum(a3) + bi;
        g_xin[(size_t)(m + 2) * Hsz + j] = f2sum(a4) + f2sum(a5) + bi;
        g_xin[(size_t)(m + 3) * Hsz + j] = f2sum(a6) + f2sum(a7) + bi;
    }
}

// ---------------------------------------------------------------------------
// Kernel 2: sequential scan. grid 256 x 128 threads, 2 rows/CTA.
// Thread (p = tid>>1, hf = tid&1): dots units j0=2p, 2p+1 over k-half
// [64hf, 64hf+64) for both rows; owns states (j0, row hf), (j0+1, row hf).
// MY row is always processed first (pointer-selected, no SELs in the loop).
// Cross-half combine = SHFL.XOR(1). One __syncthreads per unfold.
// ---------------------------------------------------------------------------
__global__ void __launch_bounds__(128, 2)
ltc_main(const float* __restrict__ W_r,
         const float* __restrict__ b_r,
         const float* __restrict__ W_fc,
         const float* __restrict__ b_fc,
         float* __restrict__ out)
{
    __shared__ float hs[2][2][HSTRIDE];   // [buf][row][padded k]
    __shared__ float red[2][64];

    const int tid  = threadIdx.x;
    const int p    = tid >> 1;            // j-pair 0..63
    const int hf   = tid & 1;             // k-half AND owned row
    const int j0   = 2 * p;
    const int base = blockIdx.x * 2;
    const int koff = hf * 68;             // 64 floats + 4-float pad at k=64
    const int jph  = j0 + (j0 >= 64 ? 4 : 0);  // padded publish index

    // Precomputed row pointers: mine first, other second (no per-unfold SEL/IMAD).
    const float* hbM[2] = { &hs[0][hf][koff],     &hs[1][hf][koff]     };
    const float* hbO[2] = { &hs[0][hf ^ 1][koff], &hs[1][hf ^ 1][koff] };
    float*       hpub[2] = { &hs[0][hf][jph],     &hs[1][hf][jph]      };

    // W_r rows j0, j0+1, cols [64hf, 64hf+64): 128 floats in registers.
    ull wA[32], wB[32];
    {
        const ulonglong2* wpA = (const ulonglong2*)(W_r + (size_t)j0 * Hsz + 64 * hf);
        const ulonglong2* wpB = (const ulonglong2*)(W_r + (size_t)(j0 + 1) * Hsz + 64 * hf);
        #pragma unroll
        for (int c = 0; c < 16; ++c) {
            ulonglong2 vA = wpA[c];
            ulonglong2 vB = wpB[c];
            wA[2 * c] = vA.x;  wA[2 * c + 1] = vA.y;
            wB[2 * c] = vB.x;  wB[2 * c + 1] = vB.y;
        }
    }

    const float2 bb2 = *(const float2*)&b_r[j0];

    float h0 = 0.f, h1 = 0.f;             // (j0, row hf), (j0+1, row hf)

    // Bootstrap: publish h=0 into buffer 0.
    hpub[0][0] = 0.f;
    hpub[0][1] = 0.f;

    const size_t xi = (size_t)(base + hf) * Ssz * Hsz + j0;
    float2 xf = *(const float2*)&g_xin[xi];

    #pragma unroll 1
    for (int t = 0; t < Ssz; ++t) {
        const float xinA = xf.x + bb2.x;
        const float xinB = xf.y + bb2.y;
        if (t + 1 < Ssz)
            xf = *(const float2*)&g_xin[xi + (size_t)(t + 1) * Hsz];

        #pragma unroll 1
        for (int u = 0; u < UNFOLDS; ++u) {
            const int rb = u & 1;                 // read buffer
            const float* hM = hbM[rb];            // my row, my k-half
            const float* hO = hbO[rb];            // other row, my k-half
            __syncthreads();   // prev publishes visible; write buf != read buf

            // dot: units j0, j0+1 x {my row, other row} over my k-half.
            // Ordering pairs FFMA2s on the same h operand for .reuse.
            ull a0 = 0ull, a1 = 0ull, b0 = 0ull, b1 = 0ull;   // my row
            ull c0 = 0ull, c1 = 0ull, d0 = 0ull, d1 = 0ull;   // other row
            #pragma unroll     // full unroll: wA/wB must stay in registers
            for (int c = 0; c < 16; ++c) {
                ulonglong2 vM = *(const ulonglong2*)(hM + 4 * c);
                ulonglong2 vO = *(const ulonglong2*)(hO + 4 * c);
                a0 = ffma2(wA[2 * c],     vM.x, a0);
                b0 = ffma2(wB[2 * c],     vM.x, b0);   // vM.x reused
                a1 = ffma2(wA[2 * c + 1], vM.y, a1);
                b1 = ffma2(wB[2 * c + 1], vM.y, b1);   // vM.y reused
                c0 = ffma2(wA[2 * c],     vO.x, c0);
                d0 = ffma2(wB[2 * c],     vO.x, d0);   // vO.x reused
                c1 = ffma2(wA[2 * c + 1], vO.y, c1);
                d1 = ffma2(wB[2 * c + 1], vO.y, d1);   // vO.y reused
            }
            const float PaM = f2sum(a0) + f2sum(a1);   // (j0,   my row)
            const float PbM = f2sum(b0) + f2sum(b1);   // (j0+1, my row)
            const float PaO = f2sum(c0) + f2sum(c1);   // (j0,   other row)
            const float PbO = f2sum(d0) + f2sum(d1);   // (j0+1, other row)

            // lane^1 owns the other row: swap other-row partials.
            const float recvA = __shfl_xor_sync(0xffffffffu, PaO, 1);
            const float recvB = __shfl_xor_sync(0xffffffffu, PbO, 1);

            h0 = 0.9f * h0 + 0.1f * ftanh(PaM + recvA + xinA);
            h1 = 0.9f * h1 + 0.1f * ftanh(PbM + recvB + xinB);

            // publish into next buffer
            float2 st;  st.x = h0;  st.y = h1;
            *(float2*)hpub[rb ^ 1] = st;
        }
    }

    // out[b] = b_fc + sum_j h[b][j] * W_fc[j]
    __syncthreads();
    {
        const float2 wfc2 = *(const float2*)&W_fc[j0];
        red[hf][p] = h0 * wfc2.x + h1 * wfc2.y;
    }
    __syncthreads();

    const int wid = tid >> 5, lane = tid & 31;
    if (wid < 2) {
        float s = red[wid][lane] + red[wid][lane + 32];
        #pragma unroll
        for (int d = 16; d > 0; d >>= 1)
            s += __shfl_xor_sync(0xffffffffu, s, d);
        if (lane == 0)
            out[base + wid] = s + b_fc[0];
    }
}

extern "C" void kernel_launch(void* const* d_in, const int* in_sizes, int n_in,
                              void* d_out, int out_size)
{
    const float* x    = (const float*)d_in[0];
    const float* W_in = (const float*)d_in[1];
    const float* b_in = (const float*)d_in[2];
    const float* W_r  = (const float*)d_in[3];
    const float* b_r  = (const float*)d_in[4];
    const float* W_fc = (const float*)d_in[5];
    const float* b_fc = (const float*)d_in[6];
    float* out = (float*)d_out;

    xin_kernel<<<(Bsz * Ssz) / 128, 128>>>(x, W_in, b_in);
    ltc_main<<<Bsz / 2, 128>>>(W_r, b_r, W_fc, b_fc, out);
}

// round 11
// speedup vs baseline: 1.2030x; 1.2030x over previous
#include <cuda_runtime.h>
#include <cstdint>

// LTC scan, round 11 — consolidation of proven wins.
// R10 post-mortem: runtime-indexed pointer arrays -> 254 regs + local-mem
// spills (L1 81%) = regression. BUT tanh.approx.f32 passed (rel_err 1.7e-6).
// R11 = R9 structure (1523us, 206 regs, 1 BAR/unfold, shfl combine, 2 CTAs/SM)
//     + MUFU.TANH
//     + FFMA2 reuse-ordering (same h operand back-to-back)
//     + SEL-free mine/other row via scalar loop-invariant offsets (no arrays).

#define Bsz 512
#define Ssz 512
#define Dsz 128
#define Hsz 128
#define UNFOLDS 6
#define HSTRIDE 136   // 128 + 4 (pad at k=64) + 4 (row-stride bank shift)

typedef unsigned long long ull;

__device__ float g_xin[(size_t)Bsz * Ssz * Hsz];   // [b][s][h] scratch

__device__ __forceinline__ ull ffma2(ull a, ull b, ull c) {
    ull d;
    asm("fma.rn.f32x2 %0, %1, %2, %3;" : "=l"(d) : "l"(a), "l"(b), "l"(c));
    return d;
}

__device__ __forceinline__ float f2sum(ull v) {
    float lo, hi;
    asm("mov.b64 {%0, %1}, %2;" : "=f"(lo), "=f"(hi) : "l"(v));
    return lo + hi;
}

__device__ __forceinline__ float ftanh(float s) {
    float y;
    asm("tanh.approx.f32 %0, %1;" : "=f"(y) : "f"(s));   // MUFU.TANH
    return y;
}

// ---------------------------------------------------------------------------
// Kernel 1: xin[b,s,j] = sum_d x[b,s,d] * W_in[j,d] + b_in[j]
// ---------------------------------------------------------------------------
__global__ void __launch_bounds__(128, 2)
xin_kernel(const float* __restrict__ x,
           const float* __restrict__ W_in,
           const float* __restrict__ b_in)
{
    __shared__ float xs[2][4 * Dsz];

    const int j = threadIdx.x;

    ull wi[64];
    {
        const ulonglong2* wp = (const ulonglong2*)(W_in + j * Dsz);
        #pragma unroll
        for (int c = 0; c < 32; ++c) {
            ulonglong2 v = wp[c];
            wi[2 * c]     = v.x;
            wi[2 * c + 1] = v.y;
        }
    }
    const float bi = b_in[j];

    const int m0 = blockIdx.x * 128;

    float xf[4];
    #pragma unroll
    for (int r = 0; r < 4; ++r)
        xf[r] = x[(size_t)(m0 + r) * Dsz + j];

    #pragma unroll 1
    for (int ch = 0; ch < 32; ++ch) {
        float* xb = xs[ch & 1];
        #pragma unroll
        for (int r = 0; r < 4; ++r)
            xb[r * Dsz + j] = xf[r];
        __syncthreads();

        if (ch < 31) {
            #pragma unroll
            for (int r = 0; r < 4; ++r)
                xf[r] = x[(size_t)(m0 + (ch + 1) * 4 + r) * Dsz + j];
        }

        ull a0 = 0ull, a1 = 0ull, a2 = 0ull, a3 = 0ull;
        ull a4 = 0ull, a5 = 0ull, a6 = 0ull, a7 = 0ull;
        #pragma unroll
        for (int c = 0; c < 32; ++c) {
            ulonglong2 v0 = *(const ulonglong2*)(xb + 0 * Dsz + 4 * c);
            ulonglong2 v1 = *(const ulonglong2*)(xb + 1 * Dsz + 4 * c);
            ulonglong2 v2 = *(const ulonglong2*)(xb + 2 * Dsz + 4 * c);
            ulonglong2 v3 = *(const ulonglong2*)(xb + 3 * Dsz + 4 * c);
            a0 = ffma2(wi[2 * c], v0.x, a0);  a1 = ffma2(wi[2 * c + 1], v0.y, a1);
            a2 = ffma2(wi[2 * c], v1.x, a2);  a3 = ffma2(wi[2 * c + 1], v1.y, a3);
            a4 = ffma2(wi[2 * c], v2.x, a4);  a5 = ffma2(wi[2 * c + 1], v2.y, a5);
            a6 = ffma2(wi[2 * c], v3.x, a6);  a7 = ffma2(wi[2 * c + 1], v3.y, a7);
        }
        const int m = m0 + ch * 4;
        g_xin[(size_t)(m + 0) * Hsz + j] = f2sum(a0) + f2sum(a1) + bi;
        g_xin[(size_t)(m + 1) * Hsz + j] = f2sum(a2) + f2sum(a3) + bi;
        g_xin[(size_t)(m + 2) * Hsz + j] = f2sum(a4) + f2sum(a5) + bi;
        g_xin[(size_t)(m + 3) * Hsz + j] = f2sum(a6) + f2sum(a7) + bi;
    }
}

// ---------------------------------------------------------------------------
// Kernel 2: sequential scan. grid 256 x 128 threads, 2 rows/CTA.
// Thread (p = tid>>1, hf = tid&1): dots units j0=2p, 2p+1 over k-half
// [64hf, 64hf+64) for both rows; owns states (j0, row hf), (j0+1, row hf).
// My row (rowM) processed first; cross-half combine = SHFL.XOR(1).
// One __syncthreads per unfold; h double-buffered via hs[u&1].
// ---------------------------------------------------------------------------
__global__ void __launch_bounds__(128, 2)
ltc_main(const float* __restrict__ W_r,
         const float* __restrict__ b_r,
         const float* __restrict__ W_fc,
         const float* __restrict__ b_fc,
         float* __restrict__ out)
{
    __shared__ float hs[2][2][HSTRIDE];   // [buf][row][padded k]
    __shared__ float red[2][64];

    const int tid  = threadIdx.x;
    const int p    = tid >> 1;            // j-pair 0..63
    const int hf   = tid & 1;             // k-half AND owned row
    const int j0   = 2 * p;
    const int base = blockIdx.x * 2;
    const int koff = hf * 68;             // 64 floats + 4-float pad at k=64
    const int jph  = j0 + (j0 >= 64 ? 4 : 0);   // padded publish index
    const int rowM = hf * HSTRIDE;              // my row offset (scalar)
    const int rowO = (hf ^ 1) * HSTRIDE;        // other row offset (scalar)
    const int offM = rowM + koff;
    const int offO = rowO + koff;
    const int offP = rowM + jph;                // publish offset

    // W_r rows j0, j0+1, cols [64hf, 64hf+64): 128 floats in registers.
    ull wA[32], wB[32];
    {
        const ulonglong2* wpA = (const ulonglong2*)(W_r + (size_t)j0 * Hsz + 64 * hf);
        const ulonglong2* wpB = (const ulonglong2*)(W_r + (size_t)(j0 + 1) * Hsz + 64 * hf);
        #pragma unroll
        for (int c = 0; c < 16; ++c) {
            ulonglong2 vA = wpA[c];
            ulonglong2 vB = wpB[c];
            wA[2 * c] = vA.x;  wA[2 * c + 1] = vA.y;
            wB[2 * c] = vB.x;  wB[2 * c + 1] = vB.y;
        }
    }

    const float2 bb2 = *(const float2*)&b_r[j0];

    float h0 = 0.f, h1 = 0.f;             // (j0, row hf), (j0+1, row hf)

    // Bootstrap: publish h=0 into buffer 0.
    hs[0][0][offP]     = 0.f;
    hs[0][0][offP + 1] = 0.f;

    const size_t xi = (size_t)(base + hf) * Ssz * Hsz + j0;
    float2 xf = *(const float2*)&g_xin[xi];

    #pragma unroll 1
    for (int t = 0; t < Ssz; ++t) {
        const float xinA = xf.x + bb2.x;
        const float xinB = xf.y + bb2.y;
        if (t + 1 < Ssz)
            xf = *(const float2*)&g_xin[xi + (size_t)(t + 1) * Hsz];

        #pragma unroll 1
        for (int u = 0; u < UNFOLDS; ++u) {
            const float* hb = hs[u & 1][0];        // read buffer base
            float*       hn = hs[(u + 1) & 1][0];  // write buffer base
            __syncthreads();   // prev publishes visible; write buf != read buf

            // dot: units j0, j0+1 x {my row, other row} over my k-half.
            // Same h operand used back-to-back -> operand .reuse.
            ull a0 = 0ull, a1 = 0ull, b0 = 0ull, b1 = 0ull;   // my row
            ull c0 = 0ull, c1 = 0ull, d0 = 0ull, d1 = 0ull;   // other row
            #pragma unroll     // full unroll: wA/wB must stay in registers
            for (int c = 0; c < 16; ++c) {
                ulonglong2 vM = *(const ulonglong2*)(hb + offM + 4 * c);
                ulonglong2 vO = *(const ulonglong2*)(hb + offO + 4 * c);
                a0 = ffma2(wA[2 * c],     vM.x, a0);
                b0 = ffma2(wB[2 * c],     vM.x, b0);   // vM.x reused
                a1 = ffma2(wA[2 * c + 1], vM.y, a1);
                b1 = ffma2(wB[2 * c + 1], vM.y, b1);   // vM.y reused
                c0 = ffma2(wA[2 * c],     vO.x, c0);
                d0 = ffma2(wB[2 * c],     vO.x, d0);   // vO.x reused
                c1 = ffma2(wA[2 * c + 1], vO.y, c1);
                d1 = ffma2(wB[2 * c + 1], vO.y, d1);   // vO.y reused
            }
            const float PaM = f2sum(a0) + f2sum(a1);   // (j0,   my row)
            const float PbM = f2sum(b0) + f2sum(b1);   // (j0+1, my row)
            const float PaO = f2sum(c0) + f2sum(c1);   // (j0,   other row)
            const float PbO = f2sum(d0) + f2sum(d1);   // (j0+1, other row)

            // lane^1 owns the other row: swap other-row partials.
            const float recvA = __shfl_xor_sync(0xffffffffu, PaO, 1);
            const float recvB = __shfl_xor_sync(0xffffffffu, PbO, 1);

            h0 = 0.9f * h0 + 0.1f * ftanh(PaM + recvA + xinA);
            h1 = 0.9f * h1 + 0.1f * ftanh(PbM + recvB + xinB);

            // publish into next buffer
            float2 st;  st.x = h0;  st.y = h1;
            *(float2*)(hn + offP) = st;
        }
    }

    // out[b] = b_fc + sum_j h[b][j] * W_fc[j]
    __syncthreads();
    {
        const float2 wfc2 = *(const float2*)&W_fc[j0];
        red[hf][p] = h0 * wfc2.x + h1 * wfc2.y;
    }
    __syncthreads();

    const int wid = tid >> 5, lane = tid & 31;
    if (wid < 2) {
        float s = red[wid][lane] + red[wid][lane + 32];
        #pragma unroll
        for (int d = 16; d > 0; d >>= 1)
            s += __shfl_xor_sync(0xffffffffu, s, d);
        if (lane == 0)
            out[base + wid] = s + b_fc[0];
    }
}

extern "C" void kernel_launch(void* const* d_in, const int* in_sizes, int n_in,
                              void* d_out, int out_size)
{
    const float* x    = (const float*)d_in[0];
    const float* W_in = (const float*)d_in[1];
    const float* b_in = (const float*)d_in[2];
    const float* W_r  = (const float*)d_in[3];
    const float* b_r  = (const float*)d_in[4];
    const float* W_fc = (const float*)d_in[5];
    const float* b_fc = (const float*)d_in[6];
    float* out = (float*)d_out;

    xin_kernel<<<(Bsz * Ssz) / 128, 128>>>(x, W_in, b_in);
    ltc_main<<<Bsz / 2, 128>>>(W_r, b_r, W_fc, b_fc, out);
}